// round 15
// baseline (speedup 1.0000x reference)
#include <cuda_runtime.h>
#include <cuda_fp16.h>
#include <math.h>
#include <stdint.h>

// ---------------- problem constants ----------------
#define CB   2
#define CS   2048
#define CHID 2048
#define CNH  16
#define CHD  128
#define CQLR 1536
#define CKVLR 512
#define CBS  (CB*CS)          // 4096
#define CCAT (CKVLR+CHD)      // 640
#define CQHD (2*CHD)          // 256

typedef __half hlf;

// ---------------- device scratch ----------------
static __device__ __align__(256) float g_qa[(size_t)CBS*CQLR];
static __device__ __align__(256) float g_opart[(size_t)2*CB*CNH*CS*CKVLR];   // 256 MB split-K partials
static __device__ __align__(256) float g_lsum[(size_t)2*CB*CNH*CS];

static __device__ __align__(256) hlf g_hid[(size_t)CBS*CHID];
static __device__ __align__(256) hlf g_qan[(size_t)CBS*CQLR];
static __device__ __align__(256) hlf g_qs[(size_t)CBS*CNH*CQHD];
static __device__ __align__(256) hlf g_ol[(size_t)CB*CNH*CS*CKVLR];
static __device__ __align__(256) hlf g_oh[(size_t)CBS*CNH*CHD];
static __device__ __align__(256) hlf g_qc[(size_t)CB*CNH*CS*CCAT];
static __device__ __align__(256) hlf g_qaw[(size_t)CQLR*CHID];
static __device__ __align__(256) hlf g_qbw[(size_t)CNH*CQHD*CQLR];
static __device__ __align__(256) hlf g_kvaw[(size_t)CCAT*CHID];
static __device__ __align__(256) hlf g_ow[(size_t)CHID*CNH*CHD];
static __device__ __align__(256) hlf g_qab[(size_t)CNH*CKVLR*CHD];     // [h][c][d]
static __device__ __align__(256) hlf g_oabt[(size_t)CNH*CHD*CKVLR];    // [h][d][c]
static __device__ __align__(256) hlf g_ckvf[(size_t)CBS*CCAT];         // keys/V, K-major fp16

// ---------------- asm helpers (sm_80-portable) ----------------
__device__ __forceinline__ uint32_t smem_u32(const void* p) {
    uint32_t a;
    asm("{ .reg .u64 t; cvta.to.shared.u64 t, %1; cvt.u32.u64 %0, t; }" : "=r"(a) : "l"(p));
    return a;
}
#define CP_ASYNC16(dst, src) \
    asm volatile("cp.async.cg.shared.global [%0], [%1], 16;" :: "r"(dst), "l"(src) : "memory")
#define CP_COMMIT() asm volatile("cp.async.commit_group;" ::: "memory")
#define CP_WAIT(n)  asm volatile("cp.async.wait_group %0;" :: "n"(n) : "memory")

#define LDSM4(r, addr) \
    asm volatile("ldmatrix.sync.aligned.m8n8.x4.shared.b16 {%0,%1,%2,%3}, [%4];" \
        : "=r"((r)[0]),"=r"((r)[1]),"=r"((r)[2]),"=r"((r)[3]) : "r"(addr))
#define LDSM4T(r, addr) \
    asm volatile("ldmatrix.sync.aligned.m8n8.x4.trans.shared.b16 {%0,%1,%2,%3}, [%4];" \
        : "=r"((r)[0]),"=r"((r)[1]),"=r"((r)[2]),"=r"((r)[3]) : "r"(addr))

#define MMA16816(d, a, b0, b1) \
    asm volatile("mma.sync.aligned.m16n8k16.row.col.f32.f16.f16.f32 " \
        "{%0,%1,%2,%3},{%4,%5,%6,%7},{%8,%9},{%0,%1,%2,%3};" \
        : "+f"((d)[0]),"+f"((d)[1]),"+f"((d)[2]),"+f"((d)[3]) \
        : "r"((a)[0]),"r"((a)[1]),"r"((a)[2]),"r"((a)[3]), "r"(b0),"r"(b1))

__device__ __forceinline__ void store_h2(float v0, float v1, hlf* hp) {
    __half2 hh; hh.x = __float2half_rn(v0); hh.y = __float2half_rn(v1);
    *reinterpret_cast<__half2*>(hp) = hh;
}

// ---------------- fp16 MMA GEMM (512 threads, 16 warps) ----------------
static constexpr int GBK = 32, STAGES = 4;
static constexpr int ASZ = 128 * GBK * 2;   // 8192 B

__device__ __forceinline__ uint32_t swz(int row, int ch) {
    return (uint32_t)(row * 64 + ((ch ^ ((row >> 1) & 3)) * 16));
}

template<int BN>
__global__ __launch_bounds__(512, 1) void mma_gemm(
    const hlf* __restrict__ A, int lda, long long aO, long long aI,
    const hlf* __restrict__ B, int ldb, long long bO, long long bI,
    float* __restrict__ C, hlf* __restrict__ Chi,
    int ldc, long long cO, long long cI,
    const float* __restrict__ bias, float alpha, int K, int zInner)
{
    constexpr int JG = BN / 64;
    constexpr int BSZ = BN * GBK * 2;
    constexpr int STAGE_B = ASZ + BSZ;

    extern __shared__ char smem_raw[];
    uint32_t sbase = smem_u32(smem_raw);

    int tid = threadIdx.x, wid = tid >> 5, lane = tid & 31;
    int z = blockIdx.z, zo = z / zInner, zi = z - zo * zInner;
    A += zo * aO + zi * aI;
    B += zo * bO + zi * bI;
    if (C)   C   += zo * cO + zi * cI;
    if (Chi) Chi += zo * cO + zi * cI;

    int bm = blockIdx.y * 128, bn = blockIdx.x * BN;
    int wm = (wid & 3) * 32;
    int wn = (wid >> 2) * (BN / 4);

    const hlf* pA = A + (long long)bm * lda;
    const hlf* pB = B + (long long)bn * ldb;

    float acc[2][2 * JG][4];
#pragma unroll
    for (int t = 0; t < 2; t++)
#pragma unroll
        for (int j = 0; j < 2 * JG; j++)
#pragma unroll
            for (int q = 0; q < 4; q++) acc[t][j][q] = 0.f;

    int nk = K / GBK;

#define ISSUE(stage_) do { \
    int st_ = (stage_) % STAGES; \
    uint32_t sb_ = sbase + st_ * STAGE_B; \
    long long k0_ = (long long)(stage_) * GBK; \
    { int r = tid >> 2, ch = tid & 3; \
      uint32_t so = swz(r, ch); \
      CP_ASYNC16(sb_ + so, pA + (long long)r * lda + k0_ + ch * 8); } \
    _Pragma("unroll") \
    for (int u = 0; u < BN / 128; u++) { \
        int idx = u * 512 + tid; int r = idx >> 2, ch = idx & 3; \
        uint32_t so = swz(r, ch); \
        CP_ASYNC16(sb_ + ASZ + so, pB + (long long)r * ldb + k0_ + ch * 8); \
    } \
} while (0)

    for (int s = 0; s < STAGES - 1; s++) {
        if (s < nk) ISSUE(s);
        CP_COMMIT();
    }

    int a_row = (lane & 15);
    int a_sel = lane >> 4;
    int b_row = (lane & 7) + ((lane >> 4) * 8);
    int b_sel = (lane >> 3) & 1;

    for (int i = 0; i < nk; i++) {
        CP_WAIT(STAGES - 2);
        __syncthreads();
        if (i + STAGES - 1 < nk) ISSUE(i + STAGES - 1);
        CP_COMMIT();

        uint32_t sb = sbase + (i % STAGES) * STAGE_B;

#pragma unroll
        for (int kh = 0; kh < 2; kh++) {
            uint32_t Af[2][4];
#pragma unroll
            for (int t = 0; t < 2; t++) {
                int row = wm + t * 16 + a_row;
                LDSM4(Af[t], sb + swz(row, 2 * kh + a_sel));
            }
#pragma unroll
            for (int jg = 0; jg < JG; jg++) {
                int row = wn + jg * 16 + b_row;
                uint32_t B4[4];
                LDSM4(B4, sb + ASZ + swz(row, 2 * kh + b_sel));
#pragma unroll
                for (int t = 0; t < 2; t++) {
                    MMA16816(acc[t][2*jg],   Af[t], B4[0], B4[1]);
                    MMA16816(acc[t][2*jg+1], Af[t], B4[2], B4[3]);
                }
            }
        }
    }
#undef ISSUE

#pragma unroll
    for (int t = 0; t < 2; t++) {
        int r0 = bm + wm + t * 16 + (lane >> 2);
#pragma unroll
        for (int j = 0; j < 2 * JG; j++) {
            int col = bn + wn + j * 8 + (lane & 3) * 2;
            float v0 = acc[t][j][0] * alpha;
            float v1 = acc[t][j][1] * alpha;
            float v2 = acc[t][j][2] * alpha;
            float v3 = acc[t][j][3] * alpha;
            if (bias) { v0 += bias[col]; v1 += bias[col + 1]; v2 += bias[col]; v3 += bias[col + 1]; }
            long long o0 = (long long)r0 * ldc + col;
            long long o1 = (long long)(r0 + 8) * ldc + col;
            if (Chi) {
                store_h2(v0, v1, Chi + o0);
                store_h2(v2, v3, Chi + o1);
            } else {
                C[o0] = v0; C[o0 + 1] = v1;
                C[o1] = v2; C[o1 + 1] = v3;
            }
        }
    }
}

// ---------------- fused flash attention v3 (split-K x2) ----------------
// CTA: 64 q rows, one (b,h), half the keys (8 j-iters of 128 keys).
// K' tile resident (10 x 16KB = 160KB). Q via 4x8KB ring. P overlays chunk 8.
// Outputs UNNORMALIZED fp32 partial O and per-row partial softmax sums.
static constexpr int FPOFF = 131072;     // P overlays chunk 8 slot
static constexpr int FQOFF = 163840;     // Q ring 4 x 8KB
static constexpr int FSMEM = 196608;     // 192 KB

__device__ __forceinline__ uint32_t psw(int row, int ch) {
    return (uint32_t)(row * 128 + ((ch ^ (row & 7)) << 4));
}

__global__ __launch_bounds__(512, 1) void flash_kernel(
    const hlf* __restrict__ Q,
    const hlf* __restrict__ Kf,
    const float* __restrict__ mask,
    float* __restrict__ Opart,      // [2][bh][2048][512] fp32
    float* __restrict__ Ls,         // [2][bh][2048]
    float scale)
{
    extern __shared__ char smem[];
    uint32_t sbase = smem_u32(smem);
    int tid = threadIdx.x, wid = tid >> 5, lane = tid & 31;
    int mg = wid & 3, cg = wid >> 2;
    int bh = blockIdx.y, b = bh >> 4;
    int q0 = blockIdx.x * 64;
    int half = blockIdx.z;
    int jlo = half * 8;

    const hlf* pQ = Q + (long long)bh * CS * CCAT + (long long)q0 * CCAT;
    const hlf* pK = Kf + (long long)b * CS * CCAT;

    int grow = tid >> 3, gch = tid & 7;
    uint32_t qsoff  = psw(grow, gch);
    long long qgoff = (long long)grow * CCAT + gch * 8;
    uint32_t ksoff0 = psw(grow, gch);
    uint32_t ksoff1 = psw(grow + 64, gch);
    long long kgoff0 = qgoff;
    long long kgoff1 = (long long)(grow + 64) * CCAT + gch * 8;

    int arow = mg * 16 + (lane & 15);
    int asel = lane >> 4;
    int brow0 = cg * 32 + (lane & 7) + ((lane >> 4) * 8);
    int brow1 = brow0 + 16;
    int bsel = (lane >> 3) & 1;
    int trow_b = (lane & 7) + (((lane >> 3) & 1) * 8);
    int tsel = lane >> 4;

    float oacc[4][4][4];
#pragma unroll
    for (int rg = 0; rg < 4; rg++)
#pragma unroll
        for (int j = 0; j < 4; j++)
#pragma unroll
            for (int q = 0; q < 4; q++) oacc[rg][j][q] = 0.f;
    float lsum0 = 0.f, lsum1 = 0.f;

    int prow0 = mg * 16 + (lane >> 2), prow1 = prow0 + 8;

    for (int j = jlo; j < jlo + 8; j++) {
        const hlf* pKj = pK + (long long)j * 128 * CCAT;

#define KISSUE(kc_) do { \
    uint32_t kb_ = sbase + (kc_) * 16384; \
    uint32_t qb_ = sbase + FQOFF + ((kc_) & 3) * 8192; \
    long long co_ = (long long)(kc_) * 64; \
    CP_ASYNC16(kb_ + ksoff0, pKj + kgoff0 + co_); \
    CP_ASYNC16(kb_ + ksoff1, pKj + kgoff1 + co_); \
    CP_ASYNC16(qb_ + qsoff,  pQ + qgoff + co_); \
    CP_COMMIT(); \
} while (0)
        KISSUE(0); KISSUE(1); KISSUE(2);

        float sacc[4][4];
#pragma unroll
        for (int n = 0; n < 4; n++)
#pragma unroll
            for (int q = 0; q < 4; q++) sacc[n][q] = 0.f;

        for (int kc = 0; kc < 10; kc++) {
            CP_WAIT(2);
            __syncthreads();
            if (kc + 3 < 10) KISSUE(kc + 3);
            else CP_COMMIT();
            uint32_t kb = sbase + kc * 16384;
            uint32_t qb = sbase + FQOFF + (kc & 3) * 8192;
#pragma unroll
            for (int kk = 0; kk < 4; kk++) {
                uint32_t A4[4];
                LDSM4(A4, qb + psw(arow, kk * 2 + asel));
                uint32_t B0[4], B1[4];
                LDSM4(B0, kb + psw(brow0, kk * 2 + bsel));
                LDSM4(B1, kb + psw(brow1, kk * 2 + bsel));
                MMA16816(sacc[0], A4, B0[0], B0[1]);
                MMA16816(sacc[1], A4, B0[2], B0[3]);
                MMA16816(sacc[2], A4, B1[0], B1[1]);
                MMA16816(sacc[3], A4, B1[2], B1[3]);
            }
        }
#undef KISSUE

        // softmax (max-free) + P fp16 write (P overlays chunk-8 slot)
        {
            const float* mrow = mask + (long long)b * CS * CS
                              + (long long)(q0 + prow0) * CS + j * 128 + cg * 32 + (lane & 3) * 2;
            uint32_t pboff = FPOFF + (cg >> 1) * 8192;
            float ladd0 = 0.f, ladd1 = 0.f;
#pragma unroll
            for (int nn = 0; nn < 4; nn++) {
                float2 m0 = *reinterpret_cast<const float2*>(mrow + nn * 8);
                float2 m1 = *reinterpret_cast<const float2*>(mrow + nn * 8 + 8 * CS);
                float p0 = __expf(sacc[nn][0] * scale + m0.x);
                float p1 = __expf(sacc[nn][1] * scale + m0.y);
                float p2 = __expf(sacc[nn][2] * scale + m1.x);
                float p3 = __expf(sacc[nn][3] * scale + m1.y);
                ladd0 += p0 + p1; ladd1 += p2 + p3;
                int c64 = (cg & 1) * 32 + nn * 8 + (lane & 3) * 2;
                uint32_t o0 = (uint32_t)(prow0 * 128 + (((c64 >> 3) ^ (prow0 & 7)) << 4) + (c64 & 7) * 2);
                uint32_t o1 = (uint32_t)(prow1 * 128 + (((c64 >> 3) ^ (prow1 & 7)) << 4) + (c64 & 7) * 2);
                store_h2(p0, p1, (hlf*)(smem + pboff + o0));
                store_h2(p2, p3, (hlf*)(smem + pboff + o1));
            }
            ladd0 += __shfl_xor_sync(~0u, ladd0, 1); ladd0 += __shfl_xor_sync(~0u, ladd0, 2);
            ladd1 += __shfl_xor_sync(~0u, ladd1, 1); ladd1 += __shfl_xor_sync(~0u, ladd1, 2);
            lsum0 += ladd0; lsum1 += ladd1;
        }
        __syncthreads();   // P visible

        // AV: warp owns col stripe [wid*32, wid*32+32), all 64 rows
        int wc = wid * 32;
#pragma unroll
        for (int kt = 0; kt < 8; kt++) {
            uint32_t pb = sbase + FPOFF + (kt >> 2) * 8192;
            int kt4 = kt & 3;
            uint32_t P4[4][4];
#pragma unroll
            for (int rg = 0; rg < 4; rg++)
                LDSM4(P4[rg], pb + psw(rg * 16 + (lane & 15), kt4 * 2 + (lane >> 4)));
            int trow = kt * 16 + trow_b;
#pragma unroll
            for (int vf = 0; vf < 2; vf++) {
                int c0 = wc + vf * 16;
                uint32_t kcb = sbase + (c0 >> 6) * 16384;
                uint32_t V4[4];
                LDSM4T(V4, kcb + psw(trow, ((c0 & 63) >> 3) + tsel));
#pragma unroll
                for (int rg = 0; rg < 4; rg++) {
                    MMA16816(oacc[rg][vf*2],   P4[rg], V4[0], V4[1]);
                    MMA16816(oacc[rg][vf*2+1], P4[rg], V4[2], V4[3]);
                }
            }
        }
        __syncthreads();   // AV reads done before next j
    }

    // finalize: row sums across 4 cg groups; write unnormalized partials
    float* Larr = reinterpret_cast<float*>(smem);
    if ((lane & 3) == 0) {
        Larr[cg * 64 + prow0] = lsum0;
        Larr[cg * 64 + prow1] = lsum1;
    }
    __syncthreads();

    long long pofs = ((long long)half * (CB * CNH) + bh) * CS * CKVLR + (long long)q0 * CKVLR;
    float* po = Opart + pofs;
    if (tid < 64) {
        Ls[(long long)half * (CB * CNH) * CS + (long long)bh * CS + q0 + tid] =
            Larr[tid] + Larr[64 + tid] + Larr[128 + tid] + Larr[192 + tid];
    }
    int wc = wid * 32;
#pragma unroll
    for (int rg = 0; rg < 4; rg++) {
        int row0 = rg * 16 + (lane >> 2), row1 = row0 + 8;
#pragma unroll
        for (int jj = 0; jj < 4; jj++) {
            int col = wc + jj * 8 + (lane & 3) * 2;
            float* a = oacc[rg][jj];
            *reinterpret_cast<float2*>(po + (long long)row0 * CKVLR + col) = make_float2(a[0], a[1]);
            *reinterpret_cast<float2*>(po + (long long)row1 * CKVLR + col) = make_float2(a[2], a[3]);
        }
    }
}

// combine split-K partials: ol = (O0+O1) / (L0+L1), fp16 out
__global__ void combine_kernel(const float* __restrict__ Opart, const float* __restrict__ Ls,
                               hlf* __restrict__ ol)
{
    const long long HSTR = (long long)(CB * CNH) * CS * CKVLR;   // elems per half
    const long long LSTR = (long long)(CB * CNH) * CS;
    long long n4 = HSTR >> 2;
    long long i4 = (long long)blockIdx.x * blockDim.x + threadIdx.x;
    long long st = (long long)gridDim.x * blockDim.x;
    for (; i4 < n4; i4 += st) {
        long long i = i4 << 2;
        long long row = i >> 9;   // / 512
        float4 a = reinterpret_cast<const float4*>(Opart)[i4];
        float4 c = reinterpret_cast<const float4*>(Opart + HSTR)[i4];
        float inv = 1.f / (Ls[row] + Ls[LSTR + row]);
        store_h2((a.x + c.x) * inv, (a.y + c.y) * inv, ol + i);
        store_h2((a.z + c.z) * inv, (a.w + c.w) * inv, ol + i + 2);
    }
}

// ---------------- conversions ----------------
__global__ void cvt_half_kernel(const float* __restrict__ s, hlf* __restrict__ d, long long n)
{
    long long n4 = n >> 2;
    long long i = (long long)blockIdx.x * blockDim.x + threadIdx.x;
    long long st = (long long)gridDim.x * blockDim.x;
    for (; i < n4; i += st) {
        float4 v = reinterpret_cast<const float4*>(s)[i];
        hlf h[4];
        h[0] = __float2half_rn(v.x); h[1] = __float2half_rn(v.y);
        h[2] = __float2half_rn(v.z); h[3] = __float2half_rn(v.w);
        *reinterpret_cast<uint2*>(d + i * 4) = *reinterpret_cast<uint2*>(h);
    }
}

// qab [h][c][d], oabT [h][d][c] from kv_b_W [c, h, 2, d]
__global__ void extract_kernel(const float* __restrict__ kvb,
                               hlf* __restrict__ qab, hlf* __restrict__ oabt)
{
    long long n = (long long)CNH * CKVLR * CHD;
    long long i = (long long)blockIdx.x * blockDim.x + threadIdx.x;
    long long st = (long long)gridDim.x * blockDim.x;
    for (; i < n; i += st) {
        {
            int c = (int)(i & 511);
            int d = (int)((i >> 9) & 127);
            int h = (int)(i >> 16);
            oabt[i] = __float2half_rn(kvb[(((long long)c * CNH + h) * 2 + 1) * CHD + d]);
        }
        {
            int d = (int)(i & 127);
            int c = (int)((i >> 7) & 511);
            int h = (int)(i >> 16);
            qab[i] = __float2half_rn(kvb[(((long long)c * CNH + h) * 2) * CHD + d]);
        }
    }
}

// ---------------- RMSNorm (fp32 in, fp16 out) ----------------
__global__ __launch_bounds__(256) void rms_kernel(const float* __restrict__ x, const float* __restrict__ w,
                                                  hlf* __restrict__ o)
{
    __shared__ float red[8];
    size_t row = blockIdx.x;
    const float* p = x + row * CQLR;
    int tid = threadIdx.x;
    float s = 0.f;
    for (int i = tid; i < CQLR; i += 256) { float v = p[i]; s += v * v; }
#pragma unroll
    for (int off = 16; off; off >>= 1) s += __shfl_xor_sync(~0u, s, off);
    if ((tid & 31) == 0) red[tid >> 5] = s;
    __syncthreads();
    float tot = 0.f;
#pragma unroll
    for (int i = 0; i < 8; i++) tot += red[i];
    float r = rsqrtf(tot + 1e-6f);
    hlf* po = o + row * CQLR;
    for (int i = tid; i < CQLR; i += 256) po[i] = __float2half_rn(p[i] * r * w[i]);
}

// ---------------- RoPE ----------------
__device__ __forceinline__ void rope_cs(int s, int i, float& c, float& sn)
{
    double invf = pow(10000.0, -(double)(2 * i) / 128.0);
    double ang = (double)s * invf;
    c = (float)cos(ang);
    sn = (float)sin(ang);
}

__global__ void rope_k_kernel(hlf* __restrict__ ckv)
{
    int idx = blockIdx.x * blockDim.x + threadIdx.x;
    if (idx >= CB * CS * 64) return;
    int i = idx & 63;
    int row = idx >> 6;
    int s = row & (CS - 1);
    float c, sn; rope_cs(s, i, c, sn);
    hlf* p = ckv + (size_t)row * CCAT + CKVLR;
    float x1 = __half2float(p[i]), x2 = __half2float(p[i + 64]);
    p[i]      = __float2half_rn(x1 * c - x2 * sn);
    p[i + 64] = __float2half_rn(x2 * c + x1 * sn);
}

__global__ void rope_q_kernel(const hlf* __restrict__ q, hlf* __restrict__ qc)
{
    int idx = blockIdx.x * blockDim.x + threadIdx.x;
    if (idx >= CB * CS * CNH * 64) return;
    int i = idx & 63;
    int h = (idx >> 6) & 15;
    int row = idx >> 10;
    int s = row & (CS - 1);
    int b = row >> 11;
    float c, sn; rope_cs(s, i, c, sn);
    long long so = (long long)row * (CNH * CQHD) + h * CQHD + CHD;
    float x1 = __half2float(q[so + i]);
    float x2 = __half2float(q[so + i + 64]);
    long long dofs = ((long long)(b * CNH + h) * CS + s) * CCAT + CKVLR;
    qc[dofs + i]      = __float2half_rn(x1 * c - x2 * sn);
    qc[dofs + i + 64] = __float2half_rn(x2 * c + x1 * sn);
}

// ---------------- launch ----------------
extern "C" void kernel_launch(void* const* d_in, const int* in_sizes, int n_in,
                              void* d_out, int out_size)
{
    const float* hidden = (const float*)d_in[0];
    const float* mask   = (const float*)d_in[1];
    const float* q_a_W  = (const float*)d_in[2];
    const float* q_a_b  = (const float*)d_in[3];
    const float* q_a_nw = (const float*)d_in[4];
    const float* q_b_W  = (const float*)d_in[5];
    const float* kv_a_W = (const float*)d_in[6];
    const float* kv_b_W = (const float*)d_in[7];
    const float* o_W    = (const float*)d_in[8];
    float* out = (float*)d_out;

    void* p;
#define SYM(v, g) cudaGetSymbolAddress(&p, g); auto* v = (decltype(&g[0]))p
    SYM(qa, g_qa);     SYM(opart, g_opart); SYM(lsum, g_lsum);
    SYM(hid, g_hid);
    SYM(qaw, g_qaw);   SYM(qbw, g_qbw);
    SYM(kvaw, g_kvaw); SYM(ow, g_ow);
    SYM(qan, g_qan);   SYM(qs, g_qs);
    SYM(qab, g_qab);   SYM(oabt, g_oabt);
    SYM(qc, g_qc);     SYM(ckvf, g_ckvf);
    SYM(ol, g_ol);     SYM(oh, g_oh);
#undef SYM

    constexpr int SMEM128 = STAGES * (ASZ + 128 * GBK * 2);  // 64 KB
    constexpr int SMEM256 = STAGES * (ASZ + 256 * GBK * 2);  // 96 KB
    cudaFuncSetAttribute(mma_gemm<128>, cudaFuncAttributeMaxDynamicSharedMemorySize, SMEM128);
    cudaFuncSetAttribute(mma_gemm<256>, cudaFuncAttributeMaxDynamicSharedMemorySize, SMEM256);
    cudaFuncSetAttribute(flash_kernel, cudaFuncAttributeMaxDynamicSharedMemorySize, FSMEM);

    const long long LS = CS;
    const int CVG = 2048;

    cvt_half_kernel<<<CVG, 256>>>(hidden, hid, (long long)CBS * CHID);
    cvt_half_kernel<<<CVG, 256>>>(q_a_W, qaw, (long long)CQLR * CHID);
    cvt_half_kernel<<<CVG, 256>>>(kv_a_W, kvaw, (long long)CCAT * CHID);

    // q_a = hidden @ q_a_W^T + bias   [4096,1536] K=2048, fp32 out  (BN=128, 384 CTAs)
    mma_gemm<128><<<dim3(CQLR / 128, CBS / 128, 1), 512, SMEM128>>>(
        hid, CHID, 0, 0, qaw, CHID, 0, 0,
        qa, nullptr, CQLR, 0, 0, q_a_b, 1.f, CHID, 1);

    // ckv = hidden @ kv_a_W^T  [4096,640] K=2048, fp16 out directly
    mma_gemm<128><<<dim3(CCAT / 128, CBS / 128, 1), 512, SMEM128>>>(
        hid, CHID, 0, 0, kvaw, CHID, 0, 0,
        nullptr, ckvf, CCAT, 0, 0, nullptr, 1.f, CHID, 1);

    rms_kernel<<<CBS, 256>>>(qa, q_a_nw, qan);
    cvt_half_kernel<<<CVG, 256>>>(q_b_W, qbw, (long long)CNH * CQHD * CQLR);

    // q = qa_norm @ q_b_W^T  [4096,4096] K=1536, fp16 out  (BN=128, 1024 CTAs)
    mma_gemm<128><<<dim3((CNH * CQHD) / 128, CBS / 128, 1), 512, SMEM128>>>(
        qan, CQLR, 0, 0, qbw, CQLR, 0, 0,
        nullptr, qs, CNH * CQHD, 0, 0, nullptr, 1.f, CQLR, 1);

    extract_kernel<<<CVG, 256>>>(kv_b_W, qab, oabt);
    rope_k_kernel<<<(CB * CS * 64) / 256, 256>>>(ckvf);
    rope_q_kernel<<<(CB * CS * CNH * 64) / 256, 256>>>(qs, qc);

    // q_lat -> qc cols [0,512)  K=128, Z=32, fp16 out
    mma_gemm<256><<<dim3(CKVLR / 256, CS / 128, CB * CNH), 512, SMEM256>>>(
        qs, CNH * CQHD, LS * CNH * CQHD, CQHD,
        qab, CHD, 0, (long long)CKVLR * CHD,
        nullptr, qc, CCAT, LS * CNH * CCAT, LS * CCAT,
        nullptr, 1.f, CHD, CNH);

    // fused attention: split-K x2 -> fp32 partials
    float scale = 1.f / sqrtf((float)CCAT);
    flash_kernel<<<dim3(CS / 64, CB * CNH, 2), 512, FSMEM>>>(
        qc, ckvf, mask, opart, lsum, scale);

    // combine partials -> ol fp16
    combine_kernel<<<4096, 256>>>(opart, lsum, ol);

    cvt_half_kernel<<<CVG, 256>>>(o_W, ow, (long long)CHID * CNH * CHD);

    // out_head = ol . o_absorb^T -> [b,s,h*128+d]  K=512, N=128, Z=32, fp16 out
    mma_gemm<128><<<dim3(1, CS / 128, CB * CNH), 512, SMEM128>>>(
        ol, CKVLR, LS * CNH * CKVLR, LS * CKVLR,
        oabt, CKVLR, 0, (long long)CHD * CKVLR,
        nullptr, oh, CNH * CHD, LS * (long long)CNH * CHD, CHD,
        nullptr, 1.f, CKVLR, CNH);

    // final = oh @ o_W^T  [4096,2048] K=2048, fp32 out
    mma_gemm<256><<<dim3(CHID / 256, CBS / 128, 1), 512, SMEM256>>>(
        oh, CNH * CHD, 0, 0, ow, CNH * CHD, 0, 0,
        out, nullptr, CHID, 0, 0, nullptr, 1.f, CNH * CHD, 1);
}

// round 16
// speedup vs baseline: 1.0451x; 1.0451x over previous
#include <cuda_runtime.h>
#include <cuda_fp16.h>
#include <math.h>
#include <stdint.h>

// ---------------- problem constants ----------------
#define CB   2
#define CS   2048
#define CHID 2048
#define CNH  16
#define CHD  128
#define CQLR 1536
#define CKVLR 512
#define CBS  (CB*CS)          // 4096
#define CCAT (CKVLR+CHD)      // 640
#define CQHD (2*CHD)          // 256

typedef __half hlf;

// ---------------- device scratch ----------------
static __device__ __align__(256) float g_qa[(size_t)CBS*CQLR];

static __device__ __align__(256) hlf g_hid[(size_t)CBS*CHID];
static __device__ __align__(256) hlf g_qan[(size_t)CBS*CQLR];
static __device__ __align__(256) hlf g_qs[(size_t)CBS*CNH*CQHD];
static __device__ __align__(256) hlf g_ol[(size_t)CB*CNH*CS*CKVLR];
static __device__ __align__(256) hlf g_oh[(size_t)CBS*CNH*CHD];
static __device__ __align__(256) hlf g_qc[(size_t)CB*CNH*CS*CCAT];
static __device__ __align__(256) hlf g_qaw[(size_t)CQLR*CHID];
static __device__ __align__(256) hlf g_qbw[(size_t)CNH*CQHD*CQLR];
static __device__ __align__(256) hlf g_kvaw[(size_t)CCAT*CHID];
static __device__ __align__(256) hlf g_ow[(size_t)CHID*CNH*CHD];
static __device__ __align__(256) hlf g_qab[(size_t)CNH*CKVLR*CHD];     // [h][c][d]
static __device__ __align__(256) hlf g_oabt[(size_t)CNH*CHD*CKVLR];    // [h][d][c]
static __device__ __align__(256) hlf g_ckvf[(size_t)CBS*CCAT];         // keys/V, K-major fp16

// ---------------- asm helpers (sm_80-portable) ----------------
__device__ __forceinline__ uint32_t smem_u32(const void* p) {
    uint32_t a;
    asm("{ .reg .u64 t; cvta.to.shared.u64 t, %1; cvt.u32.u64 %0, t; }" : "=r"(a) : "l"(p));
    return a;
}
#define CP_ASYNC16(dst, src) \
    asm volatile("cp.async.cg.shared.global [%0], [%1], 16;" :: "r"(dst), "l"(src) : "memory")
#define CP_COMMIT() asm volatile("cp.async.commit_group;" ::: "memory")
#define CP_WAIT(n)  asm volatile("cp.async.wait_group %0;" :: "n"(n) : "memory")

#define LDSM4(r, addr) \
    asm volatile("ldmatrix.sync.aligned.m8n8.x4.shared.b16 {%0,%1,%2,%3}, [%4];" \
        : "=r"((r)[0]),"=r"((r)[1]),"=r"((r)[2]),"=r"((r)[3]) : "r"(addr))
#define LDSM4T(r, addr) \
    asm volatile("ldmatrix.sync.aligned.m8n8.x4.trans.shared.b16 {%0,%1,%2,%3}, [%4];" \
        : "=r"((r)[0]),"=r"((r)[1]),"=r"((r)[2]),"=r"((r)[3]) : "r"(addr))

#define MMA16816(d, a, b0, b1) \
    asm volatile("mma.sync.aligned.m16n8k16.row.col.f32.f16.f16.f32 " \
        "{%0,%1,%2,%3},{%4,%5,%6,%7},{%8,%9},{%0,%1,%2,%3};" \
        : "+f"((d)[0]),"+f"((d)[1]),"+f"((d)[2]),"+f"((d)[3]) \
        : "r"((a)[0]),"r"((a)[1]),"r"((a)[2]),"r"((a)[3]), "r"(b0),"r"(b1))

__device__ __forceinline__ void store_h2(float v0, float v1, hlf* hp) {
    __half2 hh; hh.x = __float2half_rn(v0); hh.y = __float2half_rn(v1);
    *reinterpret_cast<__half2*>(hp) = hh;
}

// ---------------- fp16 MMA GEMM (512 threads, 16 warps) ----------------
static constexpr int GBK = 32, STAGES = 4;
static constexpr int ASZ = 128 * GBK * 2;   // 8192 B

__device__ __forceinline__ uint32_t swz(int row, int ch) {
    return (uint32_t)(row * 64 + ((ch ^ ((row >> 1) & 3)) * 16));
}

template<int BN>
__global__ __launch_bounds__(512, 1) void mma_gemm(
    const hlf* __restrict__ A, int lda, long long aO, long long aI,
    const hlf* __restrict__ B, int ldb, long long bO, long long bI,
    float* __restrict__ C, hlf* __restrict__ Chi,
    int ldc, long long cO, long long cI,
    const float* __restrict__ bias, float alpha, int K, int zInner)
{
    constexpr int JG = BN / 64;
    constexpr int BSZ = BN * GBK * 2;
    constexpr int STAGE_B = ASZ + BSZ;

    extern __shared__ char smem_raw[];
    uint32_t sbase = smem_u32(smem_raw);

    int tid = threadIdx.x, wid = tid >> 5, lane = tid & 31;
    int z = blockIdx.z, zo = z / zInner, zi = z - zo * zInner;
    A += zo * aO + zi * aI;
    B += zo * bO + zi * bI;
    if (C)   C   += zo * cO + zi * cI;
    if (Chi) Chi += zo * cO + zi * cI;

    int bm = blockIdx.y * 128, bn = blockIdx.x * BN;
    int wm = (wid & 3) * 32;
    int wn = (wid >> 2) * (BN / 4);

    const hlf* pA = A + (long long)bm * lda;
    const hlf* pB = B + (long long)bn * ldb;

    float acc[2][2 * JG][4];
#pragma unroll
    for (int t = 0; t < 2; t++)
#pragma unroll
        for (int j = 0; j < 2 * JG; j++)
#pragma unroll
            for (int q = 0; q < 4; q++) acc[t][j][q] = 0.f;

    int nk = K / GBK;

#define ISSUE(stage_) do { \
    int st_ = (stage_) % STAGES; \
    uint32_t sb_ = sbase + st_ * STAGE_B; \
    long long k0_ = (long long)(stage_) * GBK; \
    { int r = tid >> 2, ch = tid & 3; \
      uint32_t so = swz(r, ch); \
      CP_ASYNC16(sb_ + so, pA + (long long)r * lda + k0_ + ch * 8); } \
    _Pragma("unroll") \
    for (int u = 0; u < BN / 128; u++) { \
        int idx = u * 512 + tid; int r = idx >> 2, ch = idx & 3; \
        uint32_t so = swz(r, ch); \
        CP_ASYNC16(sb_ + ASZ + so, pB + (long long)r * ldb + k0_ + ch * 8); \
    } \
} while (0)

    for (int s = 0; s < STAGES - 1; s++) {
        if (s < nk) ISSUE(s);
        CP_COMMIT();
    }

    int a_row = (lane & 15);
    int a_sel = lane >> 4;
    int b_row = (lane & 7) + ((lane >> 4) * 8);
    int b_sel = (lane >> 3) & 1;

    for (int i = 0; i < nk; i++) {
        CP_WAIT(STAGES - 2);
        __syncthreads();
        if (i + STAGES - 1 < nk) ISSUE(i + STAGES - 1);
        CP_COMMIT();

        uint32_t sb = sbase + (i % STAGES) * STAGE_B;

#pragma unroll
        for (int kh = 0; kh < 2; kh++) {
            uint32_t Af[2][4];
#pragma unroll
            for (int t = 0; t < 2; t++) {
                int row = wm + t * 16 + a_row;
                LDSM4(Af[t], sb + swz(row, 2 * kh + a_sel));
            }
#pragma unroll
            for (int jg = 0; jg < JG; jg++) {
                int row = wn + jg * 16 + b_row;
                uint32_t B4[4];
                LDSM4(B4, sb + ASZ + swz(row, 2 * kh + b_sel));
#pragma unroll
                for (int t = 0; t < 2; t++) {
                    MMA16816(acc[t][2*jg],   Af[t], B4[0], B4[1]);
                    MMA16816(acc[t][2*jg+1], Af[t], B4[2], B4[3]);
                }
            }
        }
    }
#undef ISSUE

#pragma unroll
    for (int t = 0; t < 2; t++) {
        int r0 = bm + wm + t * 16 + (lane >> 2);
#pragma unroll
        for (int j = 0; j < 2 * JG; j++) {
            int col = bn + wn + j * 8 + (lane & 3) * 2;
            float v0 = acc[t][j][0] * alpha;
            float v1 = acc[t][j][1] * alpha;
            float v2 = acc[t][j][2] * alpha;
            float v3 = acc[t][j][3] * alpha;
            if (bias) { v0 += bias[col]; v1 += bias[col + 1]; v2 += bias[col]; v3 += bias[col + 1]; }
            long long o0 = (long long)r0 * ldc + col;
            long long o1 = (long long)(r0 + 8) * ldc + col;
            if (Chi) {
                store_h2(v0, v1, Chi + o0);
                store_h2(v2, v3, Chi + o1);
            } else {
                C[o0] = v0; C[o0 + 1] = v1;
                C[o1] = v2; C[o1 + 1] = v3;
            }
        }
    }
}

// ---------------- fused flash attention v2 (R14 configuration) ----------------
// CTA: 64 q rows, one (b,h). Per j-iter: 128-key K' tile fully resident
// (10 chunks x 16KB = 160KB). Q streamed via 4x8KB ring. P overlays chunk 8.
// V = chunks 0..7 re-read in AV. Grid 1024 CTAs (6.92 waves, ~1% tail).
static constexpr int FPOFF = 131072;     // P overlays chunk 8 slot
static constexpr int FQOFF = 163840;     // Q ring 4 x 8KB
static constexpr int FSMEM = 196608;     // 192 KB

__device__ __forceinline__ uint32_t psw(int row, int ch) {
    return (uint32_t)(row * 128 + ((ch ^ (row & 7)) << 4));
}

__global__ __launch_bounds__(512, 1) void flash_kernel(
    const hlf* __restrict__ Q,
    const hlf* __restrict__ Kf,
    const float* __restrict__ mask,
    hlf* __restrict__ O,
    float scale)
{
    extern __shared__ char smem[];
    uint32_t sbase = smem_u32(smem);
    int tid = threadIdx.x, wid = tid >> 5, lane = tid & 31;
    int mg = wid & 3, cg = wid >> 2;
    int bh = blockIdx.y, b = bh >> 4;
    int q0 = blockIdx.x * 64;

    const hlf* pQ = Q + (long long)bh * CS * CCAT + (long long)q0 * CCAT;
    const hlf* pK = Kf + (long long)b * CS * CCAT;

    int grow = tid >> 3, gch = tid & 7;
    uint32_t qsoff  = psw(grow, gch);
    long long qgoff = (long long)grow * CCAT + gch * 8;
    uint32_t ksoff0 = psw(grow, gch);
    uint32_t ksoff1 = psw(grow + 64, gch);
    long long kgoff0 = qgoff;
    long long kgoff1 = (long long)(grow + 64) * CCAT + gch * 8;

    int arow = mg * 16 + (lane & 15);
    int asel = lane >> 4;
    int brow0 = cg * 32 + (lane & 7) + ((lane >> 4) * 8);
    int brow1 = brow0 + 16;
    int bsel = (lane >> 3) & 1;
    int trow_b = (lane & 7) + (((lane >> 3) & 1) * 8);
    int tsel = lane >> 4;

    float oacc[4][4][4];
#pragma unroll
    for (int rg = 0; rg < 4; rg++)
#pragma unroll
        for (int j = 0; j < 4; j++)
#pragma unroll
            for (int q = 0; q < 4; q++) oacc[rg][j][q] = 0.f;
    float lsum0 = 0.f, lsum1 = 0.f;

    int prow0 = mg * 16 + (lane >> 2), prow1 = prow0 + 8;

    for (int j = 0; j < 16; j++) {
        const hlf* pKj = pK + (long long)j * 128 * CCAT;

#define KISSUE(kc_) do { \
    uint32_t kb_ = sbase + (kc_) * 16384; \
    uint32_t qb_ = sbase + FQOFF + ((kc_) & 3) * 8192; \
    long long co_ = (long long)(kc_) * 64; \
    CP_ASYNC16(kb_ + ksoff0, pKj + kgoff0 + co_); \
    CP_ASYNC16(kb_ + ksoff1, pKj + kgoff1 + co_); \
    CP_ASYNC16(qb_ + qsoff,  pQ + qgoff + co_); \
    CP_COMMIT(); \
} while (0)
        KISSUE(0); KISSUE(1); KISSUE(2);

        float sacc[4][4];
#pragma unroll
        for (int n = 0; n < 4; n++)
#pragma unroll
            for (int q = 0; q < 4; q++) sacc[n][q] = 0.f;

        for (int kc = 0; kc < 10; kc++) {
            CP_WAIT(2);
            __syncthreads();
            if (kc + 3 < 10) KISSUE(kc + 3);
            else CP_COMMIT();
            uint32_t kb = sbase + kc * 16384;
            uint32_t qb = sbase + FQOFF + (kc & 3) * 8192;
#pragma unroll
            for (int kk = 0; kk < 4; kk++) {
                uint32_t A4[4];
                LDSM4(A4, qb + psw(arow, kk * 2 + asel));
                uint32_t B0[4], B1[4];
                LDSM4(B0, kb + psw(brow0, kk * 2 + bsel));
                LDSM4(B1, kb + psw(brow1, kk * 2 + bsel));
                MMA16816(sacc[0], A4, B0[0], B0[1]);
                MMA16816(sacc[1], A4, B0[2], B0[3]);
                MMA16816(sacc[2], A4, B1[0], B1[1]);
                MMA16816(sacc[3], A4, B1[2], B1[3]);
            }
        }
#undef KISSUE

        // softmax (max-free) + P fp16 write (P overlays chunk-8 slot)
        {
            const float* mrow = mask + (long long)b * CS * CS
                              + (long long)(q0 + prow0) * CS + j * 128 + cg * 32 + (lane & 3) * 2;
            uint32_t pboff = FPOFF + (cg >> 1) * 8192;
            float ladd0 = 0.f, ladd1 = 0.f;
#pragma unroll
            for (int nn = 0; nn < 4; nn++) {
                float2 m0 = *reinterpret_cast<const float2*>(mrow + nn * 8);
                float2 m1 = *reinterpret_cast<const float2*>(mrow + nn * 8 + 8 * CS);
                float p0 = __expf(sacc[nn][0] * scale + m0.x);
                float p1 = __expf(sacc[nn][1] * scale + m0.y);
                float p2 = __expf(sacc[nn][2] * scale + m1.x);
                float p3 = __expf(sacc[nn][3] * scale + m1.y);
                ladd0 += p0 + p1; ladd1 += p2 + p3;
                int c64 = (cg & 1) * 32 + nn * 8 + (lane & 3) * 2;
                uint32_t o0 = (uint32_t)(prow0 * 128 + (((c64 >> 3) ^ (prow0 & 7)) << 4) + (c64 & 7) * 2);
                uint32_t o1 = (uint32_t)(prow1 * 128 + (((c64 >> 3) ^ (prow1 & 7)) << 4) + (c64 & 7) * 2);
                store_h2(p0, p1, (hlf*)(smem + pboff + o0));
                store_h2(p2, p3, (hlf*)(smem + pboff + o1));
            }
            ladd0 += __shfl_xor_sync(~0u, ladd0, 1); ladd0 += __shfl_xor_sync(~0u, ladd0, 2);
            ladd1 += __shfl_xor_sync(~0u, ladd1, 1); ladd1 += __shfl_xor_sync(~0u, ladd1, 2);
            lsum0 += ladd0; lsum1 += ladd1;
        }
        __syncthreads();   // P visible to all warps

        // AV: O += P*V; warp owns col stripe [wid*32, wid*32+32), all 64 rows
        int wc = wid * 32;
#pragma unroll
        for (int kt = 0; kt < 8; kt++) {
            uint32_t pb = sbase + FPOFF + (kt >> 2) * 8192;
            int kt4 = kt & 3;
            uint32_t P4[4][4];
#pragma unroll
            for (int rg = 0; rg < 4; rg++)
                LDSM4(P4[rg], pb + psw(rg * 16 + (lane & 15), kt4 * 2 + (lane >> 4)));
            int trow = kt * 16 + trow_b;
#pragma unroll
            for (int vf = 0; vf < 2; vf++) {
                int c0 = wc + vf * 16;
                uint32_t kcb = sbase + (c0 >> 6) * 16384;
                uint32_t V4[4];
                LDSM4T(V4, kcb + psw(trow, ((c0 & 63) >> 3) + tsel));
#pragma unroll
                for (int rg = 0; rg < 4; rg++) {
                    MMA16816(oacc[rg][vf*2],   P4[rg], V4[0], V4[1]);
                    MMA16816(oacc[rg][vf*2+1], P4[rg], V4[2], V4[3]);
                }
            }
        }
        __syncthreads();   // AV (K/P) reads done before next j overwrites them
    }

    // finalize
    float* Larr = reinterpret_cast<float*>(smem);
    if ((lane & 3) == 0) {
        Larr[cg * 64 + prow0] = lsum0;
        Larr[cg * 64 + prow1] = lsum1;
    }
    __syncthreads();

    hlf* po = O + (long long)bh * CS * CKVLR + (long long)q0 * CKVLR;
    int wc = wid * 32;
#pragma unroll
    for (int rg = 0; rg < 4; rg++) {
        int row0 = rg * 16 + (lane >> 2), row1 = row0 + 8;
        float inv0 = 1.f / (Larr[row0] + Larr[64 + row0] + Larr[128 + row0] + Larr[192 + row0]);
        float inv1 = 1.f / (Larr[row1] + Larr[64 + row1] + Larr[128 + row1] + Larr[192 + row1]);
#pragma unroll
        for (int jj = 0; jj < 4; jj++) {
            int col = wc + jj * 8 + (lane & 3) * 2;
            float* a = oacc[rg][jj];
            store_h2(a[0] * inv0, a[1] * inv0, po + (long long)row0 * CKVLR + col);
            store_h2(a[2] * inv1, a[3] * inv1, po + (long long)row1 * CKVLR + col);
        }
    }
}

// ---------------- conversions ----------------
__global__ void cvt_half_kernel(const float* __restrict__ s, hlf* __restrict__ d, long long n)
{
    long long n4 = n >> 2;
    long long i = (long long)blockIdx.x * blockDim.x + threadIdx.x;
    long long st = (long long)gridDim.x * blockDim.x;
    for (; i < n4; i += st) {
        float4 v = reinterpret_cast<const float4*>(s)[i];
        hlf h[4];
        h[0] = __float2half_rn(v.x); h[1] = __float2half_rn(v.y);
        h[2] = __float2half_rn(v.z); h[3] = __float2half_rn(v.w);
        *reinterpret_cast<uint2*>(d + i * 4) = *reinterpret_cast<uint2*>(h);
    }
}

// qab [h][c][d], oabT [h][d][c] from kv_b_W [c, h, 2, d]
__global__ void extract_kernel(const float* __restrict__ kvb,
                               hlf* __restrict__ qab, hlf* __restrict__ oabt)
{
    long long n = (long long)CNH * CKVLR * CHD;
    long long i = (long long)blockIdx.x * blockDim.x + threadIdx.x;
    long long st = (long long)gridDim.x * blockDim.x;
    for (; i < n; i += st) {
        {
            int c = (int)(i & 511);
            int d = (int)((i >> 9) & 127);
            int h = (int)(i >> 16);
            oabt[i] = __float2half_rn(kvb[(((long long)c * CNH + h) * 2 + 1) * CHD + d]);
        }
        {
            int d = (int)(i & 127);
            int c = (int)((i >> 7) & 511);
            int h = (int)(i >> 16);
            qab[i] = __float2half_rn(kvb[(((long long)c * CNH + h) * 2) * CHD + d]);
        }
    }
}

// ---------------- RMSNorm (fp32 in, fp16 out) ----------------
__global__ __launch_bounds__(256) void rms_kernel(const float* __restrict__ x, const float* __restrict__ w,
                                                  hlf* __restrict__ o)
{
    __shared__ float red[8];
    size_t row = blockIdx.x;
    const float* p = x + row * CQLR;
    int tid = threadIdx.x;
    float s = 0.f;
    for (int i = tid; i < CQLR; i += 256) { float v = p[i]; s += v * v; }
#pragma unroll
    for (int off = 16; off; off >>= 1) s += __shfl_xor_sync(~0u, s, off);
    if ((tid & 31) == 0) red[tid >> 5] = s;
    __syncthreads();
    float tot = 0.f;
#pragma unroll
    for (int i = 0; i < 8; i++) tot += red[i];
    float r = rsqrtf(tot + 1e-6f);
    hlf* po = o + row * CQLR;
    for (int i = tid; i < CQLR; i += 256) po[i] = __float2half_rn(p[i] * r * w[i]);
}

// ---------------- RoPE ----------------
__device__ __forceinline__ void rope_cs(int s, int i, float& c, float& sn)
{
    double invf = pow(10000.0, -(double)(2 * i) / 128.0);
    double ang = (double)s * invf;
    c = (float)cos(ang);
    sn = (float)sin(ang);
}

__global__ void rope_k_kernel(hlf* __restrict__ ckv)
{
    int idx = blockIdx.x * blockDim.x + threadIdx.x;
    if (idx >= CB * CS * 64) return;
    int i = idx & 63;
    int row = idx >> 6;
    int s = row & (CS - 1);
    float c, sn; rope_cs(s, i, c, sn);
    hlf* p = ckv + (size_t)row * CCAT + CKVLR;
    float x1 = __half2float(p[i]), x2 = __half2float(p[i + 64]);
    p[i]      = __float2half_rn(x1 * c - x2 * sn);
    p[i + 64] = __float2half_rn(x2 * c + x1 * sn);
}

__global__ void rope_q_kernel(const hlf* __restrict__ q, hlf* __restrict__ qc)
{
    int idx = blockIdx.x * blockDim.x + threadIdx.x;
    if (idx >= CB * CS * CNH * 64) return;
    int i = idx & 63;
    int h = (idx >> 6) & 15;
    int row = idx >> 10;
    int s = row & (CS - 1);
    int b = row >> 11;
    float c, sn; rope_cs(s, i, c, sn);
    long long so = (long long)row * (CNH * CQHD) + h * CQHD + CHD;
    float x1 = __half2float(q[so + i]);
    float x2 = __half2float(q[so + i + 64]);
    long long dofs = ((long long)(b * CNH + h) * CS + s) * CCAT + CKVLR;
    qc[dofs + i]      = __float2half_rn(x1 * c - x2 * sn);
    qc[dofs + i + 64] = __float2half_rn(x2 * c + x1 * sn);
}

// ---------------- launch ----------------
extern "C" void kernel_launch(void* const* d_in, const int* in_sizes, int n_in,
                              void* d_out, int out_size)
{
    const float* hidden = (const float*)d_in[0];
    const float* mask   = (const float*)d_in[1];
    const float* q_a_W  = (const float*)d_in[2];
    const float* q_a_b  = (const float*)d_in[3];
    const float* q_a_nw = (const float*)d_in[4];
    const float* q_b_W  = (const float*)d_in[5];
    const float* kv_a_W = (const float*)d_in[6];
    const float* kv_b_W = (const float*)d_in[7];
    const float* o_W    = (const float*)d_in[8];
    float* out = (float*)d_out;

    void* p;
#define SYM(v, g) cudaGetSymbolAddress(&p, g); auto* v = (decltype(&g[0]))p
    SYM(qa, g_qa);
    SYM(hid, g_hid);
    SYM(qaw, g_qaw);   SYM(qbw, g_qbw);
    SYM(kvaw, g_kvaw); SYM(ow, g_ow);
    SYM(qan, g_qan);   SYM(qs, g_qs);
    SYM(qab, g_qab);   SYM(oabt, g_oabt);
    SYM(qc, g_qc);     SYM(ckvf, g_ckvf);
    SYM(ol, g_ol);     SYM(oh, g_oh);
#undef SYM

    constexpr int SMEM128 = STAGES * (ASZ + 128 * GBK * 2);  // 64 KB
    constexpr int SMEM256 = STAGES * (ASZ + 256 * GBK * 2);  // 96 KB
    cudaFuncSetAttribute(mma_gemm<128>, cudaFuncAttributeMaxDynamicSharedMemorySize, SMEM128);
    cudaFuncSetAttribute(mma_gemm<256>, cudaFuncAttributeMaxDynamicSharedMemorySize, SMEM256);
    cudaFuncSetAttribute(flash_kernel, cudaFuncAttributeMaxDynamicSharedMemorySize, FSMEM);

    const long long LS = CS;
    const int CVG = 2048;

    cvt_half_kernel<<<CVG, 256>>>(hidden, hid, (long long)CBS * CHID);
    cvt_half_kernel<<<CVG, 256>>>(q_a_W, qaw, (long long)CQLR * CHID);
    cvt_half_kernel<<<CVG, 256>>>(kv_a_W, kvaw, (long long)CCAT * CHID);

    // q_a = hidden @ q_a_W^T + bias  [4096,1536] K=2048, fp32 out (BN=128: measured faster)
    mma_gemm<128><<<dim3(CQLR / 128, CBS / 128, 1), 512, SMEM128>>>(
        hid, CHID, 0, 0, qaw, CHID, 0, 0,
        qa, nullptr, CQLR, 0, 0, q_a_b, 1.f, CHID, 1);

    // ckv = hidden @ kv_a_W^T  [4096,640] K=2048, fp16 out directly
    mma_gemm<128><<<dim3(CCAT / 128, CBS / 128, 1), 512, SMEM128>>>(
        hid, CHID, 0, 0, kvaw, CHID, 0, 0,
        nullptr, ckvf, CCAT, 0, 0, nullptr, 1.f, CHID, 1);

    rms_kernel<<<CBS, 256>>>(qa, q_a_nw, qan);
    cvt_half_kernel<<<CVG, 256>>>(q_b_W, qbw, (long long)CNH * CQHD * CQLR);

    // q = qa_norm @ q_b_W^T  [4096,4096] K=1536, fp16 out (BN=256)
    mma_gemm<256><<<dim3((CNH * CQHD) / 256, CBS / 128, 1), 512, SMEM256>>>(
        qan, CQLR, 0, 0, qbw, CQLR, 0, 0,
        nullptr, qs, CNH * CQHD, 0, 0, nullptr, 1.f, CQLR, 1);

    extract_kernel<<<CVG, 256>>>(kv_b_W, qab, oabt);
    rope_k_kernel<<<(CB * CS * 64) / 256, 256>>>(ckvf);
    rope_q_kernel<<<(CB * CS * CNH * 64) / 256, 256>>>(qs, qc);

    // q_lat -> qc cols [0,512)  K=128, Z=32, fp16 out
    mma_gemm<256><<<dim3(CKVLR / 256, CS / 128, CB * CNH), 512, SMEM256>>>(
        qs, CNH * CQHD, LS * CNH * CQHD, CQHD,
        qab, CHD, 0, (long long)CKVLR * CHD,
        nullptr, qc, CCAT, LS * CNH * CCAT, LS * CCAT,
        nullptr, 1.f, CHD, CNH);

    // fused attention: scores + softmax + AV -> ol (fp16)
    float scale = 1.f / sqrtf((float)CCAT);
    flash_kernel<<<dim3(CS / 64, CB * CNH), 512, FSMEM>>>(
        qc, ckvf, mask, ol, scale);

    cvt_half_kernel<<<CVG, 256>>>(o_W, ow, (long long)CHID * CNH * CHD);

    // out_head = ol . o_absorb^T -> [b,s,h*128+d]  K=512, N=128, Z=32, fp16 out
    mma_gemm<128><<<dim3(1, CS / 128, CB * CNH), 512, SMEM128>>>(
        ol, CKVLR, LS * CNH * CKVLR, LS * CKVLR,
        oabt, CKVLR, 0, (long long)CHD * CKVLR,
        nullptr, oh, CNH * CHD, LS * (long long)CNH * CHD, CHD,
        nullptr, 1.f, CKVLR, CNH);

    // final = oh @ o_W^T  [4096,2048] K=2048, fp32 out
    mma_gemm<256><<<dim3(CHID / 256, CBS / 128, 1), 512, SMEM256>>>(
        oh, CNH * CHD, 0, 0, ow, CNH * CHD, 0, 0,
        out, nullptr, CHID, 0, 0, nullptr, 1.f, CNH * CHD, 1);
}